// round 7
// baseline (speedup 1.0000x reference)
#include <cuda_runtime.h>

#define NROWS 524288
#define DDIM  256
#define NSEG  128
#define ROWS_PER_BLOCK 64
#define GRID  (NROWS / ROWS_PER_BLOCK)   // 8192
#define PREP_BLOCKS 32

// ---------------- scratch (device globals; no allocation) ----------------
__device__ __align__(16) float g_u[DDIM];   // Wk @ ones
__device__ __align__(16) float g_v[DDIM];   // Wv @ Wo
__device__ float    g_num[NSEG];
__device__ float    g_den[NSEG];
__device__ unsigned g_ready;                // prep completion flag (zero-init)
__device__ unsigned g_done;                 // finalize ticket  (zero-init)

// ---------------- single fused kernel ----------------
// blocks 0..31: compute weight collapse (warp per d), release g_ready.
// all blocks: spin (briefly) for weights, hoist u/v into 4 float4 REGISTERS
// (no shared-memory reads in the hot loop -> l1tex carries only the LDGs),
// then each warp streams 8 consecutive rows: 2 LDG.128 + dual dot + 5-step
// xor... down reduction + exp + register-carried segment accumulation.
// Last block (ticket) finalizes out[] and resets all globals for replay.
__global__ void __launch_bounds__(256, 6)
fused_kernel(const float* __restrict__ x, const int* __restrict__ seg,
             const float* __restrict__ Wk, const float* __restrict__ Wv,
             const float* __restrict__ bv, const float* __restrict__ Wo,
             const float* __restrict__ bo, float* __restrict__ out)
{
    __shared__ float s_num[NSEG];
    __shared__ float s_den[NSEG];
    __shared__ bool  s_last;

    int t    = threadIdx.x;
    int lane = t & 31;
    int warp = t >> 5;

    if (t < NSEG) { s_num[t] = 0.0f; s_den[t] = 0.0f; }

    // ---- embedded prep: blocks 0..31 (guaranteed wave-1 residents) ----
    if (blockIdx.x < PREP_BLOCKS) {
        int d = blockIdx.x * 8 + warp;
        const float4* wk  = reinterpret_cast<const float4*>(Wk + (size_t)d * DDIM);
        const float4* wv  = reinterpret_cast<const float4*>(Wv + (size_t)d * DDIM);
        const float4* wo4 = reinterpret_cast<const float4*>(Wo);
        float su = 0.0f, sv = 0.0f;
#pragma unroll
        for (int i = 0; i < 2; i++) {
            int idx = lane + 32 * i;
            float4 k = wk[idx], v = wv[idx], o = wo4[idx];
            su += (k.x + k.y) + (k.z + k.w);
            sv += v.x * o.x + v.y * o.y + v.z * o.z + v.w * o.w;
        }
#pragma unroll
        for (int o = 16; o > 0; o >>= 1) {
            su += __shfl_down_sync(0xFFFFFFFFu, su, o);
            sv += __shfl_down_sync(0xFFFFFFFFu, sv, o);
        }
        if (lane == 0) { g_u[d] = su; g_v[d] = sv; }
        __syncthreads();
        if (t == 0) { __threadfence(); atomicAdd(&g_ready, 1u); }
    }

    // ---- wait for weights (first read of g_u/g_v this launch; L1 is
    //      flushed per launch so no stale data is possible) ----
    if (t == 0) {
        while (atomicAdd(&g_ready, 0u) < PREP_BLOCKS) __nanosleep(128);
    }
    __syncthreads();

    const float4* gu4 = reinterpret_cast<const float4*>(g_u);
    const float4* gv4 = reinterpret_cast<const float4*>(g_v);
    float4 ua = gu4[lane], ub = gu4[32 + lane];
    float4 va = gv4[lane], vb = gv4[32 + lane];

    int row0 = blockIdx.x * ROWS_PER_BLOCK + warp * 8;
    float accN = 0.0f, accD = 0.0f;
    int curSeg = -1;

#pragma unroll 1
    for (int r = 0; r < 8; r++) {
        int row = row0 + r;
        const float4* xp = reinterpret_cast<const float4*>(x) + (size_t)row * (DDIM / 4);
        float4 x0 = __ldcs(xp + lane);
        float4 x1 = __ldcs(xp + 32 + lane);

        float lg, vl;
        lg = x0.x * ua.x;           vl = x0.x * va.x;
        lg = fmaf(x0.y, ua.y, lg);  vl = fmaf(x0.y, va.y, vl);
        lg = fmaf(x0.z, ua.z, lg);  vl = fmaf(x0.z, va.z, vl);
        lg = fmaf(x0.w, ua.w, lg);  vl = fmaf(x0.w, va.w, vl);
        lg = fmaf(x1.x, ub.x, lg);  vl = fmaf(x1.x, vb.x, vl);
        lg = fmaf(x1.y, ub.y, lg);  vl = fmaf(x1.y, vb.y, vl);
        lg = fmaf(x1.z, ub.z, lg);  vl = fmaf(x1.z, vb.z, vl);
        lg = fmaf(x1.w, ub.w, lg);  vl = fmaf(x1.w, vb.w, vl);

#pragma unroll
        for (int o = 16; o > 0; o >>= 1) {
            lg += __shfl_down_sync(0xFFFFFFFFu, lg, o);
            vl += __shfl_down_sync(0xFFFFFFFFu, vl, o);
        }

        if (lane == 0) {
            int s = seg[row];
            if (s != curSeg) {                // sorted segments: rare
                if (curSeg >= 0) {
                    atomicAdd(&s_num[curSeg], accN);
                    atomicAdd(&s_den[curSeg], accD);
                }
                curSeg = s; accN = 0.0f; accD = 0.0f;
            }
            float e = __expf(lg);
            accD += e;
            accN = fmaf(e, vl, accN);
        }
    }
    if (lane == 0 && curSeg >= 0) {
        atomicAdd(&s_num[curSeg], accN);
        atomicAdd(&s_den[curSeg], accD);
    }

    __syncthreads();
    if (t < NSEG && s_den[t] != 0.0f) {
        atomicAdd(&g_num[t], s_num[t]);
        atomicAdd(&g_den[t], s_den[t]);
    }

    // ---- last-block finalize + state reset ----
    __threadfence();
    __syncthreads();
    if (t == 0) {
        unsigned ticket = atomicAdd(&g_done, 1u);
        s_last = (ticket == (unsigned)(GRID - 1));
    }
    __syncthreads();
    if (!s_last) return;

    __shared__ float s_red[256];
    s_red[t] = bv[t] * Wo[t];
    __syncthreads();
#pragma unroll
    for (int o = 128; o > 0; o >>= 1) {
        if (t < o) s_red[t] += s_red[t + o];
        __syncthreads();
    }
    float c2 = s_red[0];
    float b  = bo[0];
    if (t < NSEG) {
        float den = g_den[t];
        out[t] = (den != 0.0f) ? (g_num[t] / den + c2 + b) : b;
    }
    __syncthreads();
    // reset globals so the next graph replay starts clean
    if (t < NSEG) { g_num[t] = 0.0f; g_den[t] = 0.0f; }
    if (t == 0)   { g_ready = 0u; g_done = 0u; __threadfence(); }
}

// ---------------- launch ----------------
extern "C" void kernel_launch(void* const* d_in, const int* in_sizes, int n_in,
                              void* d_out, int out_size) {
    const float* x   = (const float*)d_in[0];
    const int*   seg = (const int*)d_in[1];
    const float* Wk  = (const float*)d_in[2];
    // d_in[3] = bk (cancels in the segment softmax; unused)
    const float* Wv  = (const float*)d_in[4];
    const float* bv  = (const float*)d_in[5];
    const float* Wo  = (const float*)d_in[6];
    const float* bo  = (const float*)d_in[7];
    float* out = (float*)d_out;

    fused_kernel<<<GRID, 256>>>(x, seg, Wk, Wv, bv, Wo, bo, out);
}

// round 8
// speedup vs baseline: 1.0214x; 1.0214x over previous
#include <cuda_runtime.h>

#define NROWS 524288
#define DDIM  256
#define NSEG  128
#define ROWS_PER_BLOCK 64
#define GRID  (NROWS / ROWS_PER_BLOCK)   // 8192
#define PREP_BLOCKS 32

// ---------------- scratch (device globals; no allocation) ----------------
__device__ __align__(16) float g_u[DDIM];   // Wk @ ones
__device__ __align__(16) float g_v[DDIM];   // Wv @ Wo
__device__ float    g_num[NSEG];
__device__ float    g_den[NSEG];
__device__ unsigned g_ready;                // prep completion (zero-init)
__device__ unsigned g_done;                 // finalize ticket (zero-init)

// ---------------- single fused kernel ----------------
// R6 hot loop (16 lanes/row, MLP=4/thread, shared weights, occ target 7/SM)
// + embedded prep in blocks 0..31 + last-block finalize/reset.
__global__ void __launch_bounds__(256, 7)
fused_kernel(const float* __restrict__ x, const int* __restrict__ seg,
             const float* __restrict__ Wk, const float* __restrict__ Wv,
             const float* __restrict__ bv, const float* __restrict__ Wo,
             const float* __restrict__ bo, float* __restrict__ out)
{
    __shared__ __align__(16) float s_u[DDIM];
    __shared__ __align__(16) float s_v[DDIM];
    __shared__ float s_num[NSEG];
    __shared__ float s_den[NSEG];
    __shared__ bool  s_last;

    int t    = threadIdx.x;
    int lane = t & 31;
    int warp = t >> 5;

    if (t < NSEG) { s_num[t] = 0.0f; s_den[t] = 0.0f; }

    // ---- embedded prep: blocks 0..31 (wave-1 residents, no deadlock) ----
    if (blockIdx.x < PREP_BLOCKS) {
        int d = blockIdx.x * 8 + warp;
        const float4* wk  = reinterpret_cast<const float4*>(Wk + (size_t)d * DDIM);
        const float4* wv  = reinterpret_cast<const float4*>(Wv + (size_t)d * DDIM);
        const float4* wo4 = reinterpret_cast<const float4*>(Wo);
        float su = 0.0f, sv = 0.0f;
#pragma unroll
        for (int i = 0; i < 2; i++) {
            int idx = lane + 32 * i;
            float4 k = wk[idx], v = wv[idx], o = wo4[idx];
            su += (k.x + k.y) + (k.z + k.w);
            sv += v.x * o.x + v.y * o.y + v.z * o.z + v.w * o.w;
        }
#pragma unroll
        for (int o = 16; o > 0; o >>= 1) {
            su += __shfl_down_sync(0xFFFFFFFFu, su, o);
            sv += __shfl_down_sync(0xFFFFFFFFu, sv, o);
        }
        if (lane == 0) { g_u[d] = su; g_v[d] = sv; }
        __syncthreads();
        if (t == 0) { __threadfence(); atomicAdd(&g_ready, 1u); }
    }

    // ---- wait for weights, stage into shared ----
    if (t == 0) {
        while (atomicAdd(&g_ready, 0u) < PREP_BLOCKS) __nanosleep(128);
    }
    __syncthreads();
    s_u[t] = g_u[t];
    s_v[t] = g_v[t];
    __syncthreads();

    int c = lane & 15;                       // lane within 16-lane row group
    int g = (warp << 1) | (lane >> 4);       // group 0..15 within block

    const float4* su = reinterpret_cast<const float4*>(s_u);
    const float4* sv = reinterpret_cast<const float4*>(s_v);

    float accN = 0.0f, accD = 0.0f;
    int curSeg = -1;

#pragma unroll 1
    for (int r = 0; r < 4; r++) {
        int row = blockIdx.x * ROWS_PER_BLOCK + r * 16 + g;
        const float4* xp = reinterpret_cast<const float4*>(x + (size_t)row * DDIM);

        // 4 independent streaming loads (MLP=4/thread, 8 LDG.128/warp)
        float4 x0 = __ldcs(&xp[c]);
        float4 x1 = __ldcs(&xp[c + 16]);
        float4 x2 = __ldcs(&xp[c + 32]);
        float4 x3 = __ldcs(&xp[c + 48]);

        float lg = 0.0f, vl = 0.0f;
        {
            float4 u0 = su[c],      v0 = sv[c];
            lg = fmaf(x0.x, u0.x, lg); lg = fmaf(x0.y, u0.y, lg);
            lg = fmaf(x0.z, u0.z, lg); lg = fmaf(x0.w, u0.w, lg);
            vl = fmaf(x0.x, v0.x, vl); vl = fmaf(x0.y, v0.y, vl);
            vl = fmaf(x0.z, v0.z, vl); vl = fmaf(x0.w, v0.w, vl);
        }
        {
            float4 u1 = su[c + 16], v1 = sv[c + 16];
            lg = fmaf(x1.x, u1.x, lg); lg = fmaf(x1.y, u1.y, lg);
            lg = fmaf(x1.z, u1.z, lg); lg = fmaf(x1.w, u1.w, lg);
            vl = fmaf(x1.x, v1.x, vl); vl = fmaf(x1.y, v1.y, vl);
            vl = fmaf(x1.z, v1.z, vl); vl = fmaf(x1.w, v1.w, vl);
        }
        {
            float4 u2 = su[c + 32], v2 = sv[c + 32];
            lg = fmaf(x2.x, u2.x, lg); lg = fmaf(x2.y, u2.y, lg);
            lg = fmaf(x2.z, u2.z, lg); lg = fmaf(x2.w, u2.w, lg);
            vl = fmaf(x2.x, v2.x, vl); vl = fmaf(x2.y, v2.y, vl);
            vl = fmaf(x2.z, v2.z, vl); vl = fmaf(x2.w, v2.w, vl);
        }
        {
            float4 u3 = su[c + 48], v3 = sv[c + 48];
            lg = fmaf(x3.x, u3.x, lg); lg = fmaf(x3.y, u3.y, lg);
            lg = fmaf(x3.z, u3.z, lg); lg = fmaf(x3.w, u3.w, lg);
            vl = fmaf(x3.x, v3.x, vl); vl = fmaf(x3.y, v3.y, vl);
            vl = fmaf(x3.z, v3.z, vl); vl = fmaf(x3.w, v3.w, vl);
        }

#pragma unroll
        for (int o = 8; o > 0; o >>= 1) {
            lg += __shfl_down_sync(0xFFFFFFFFu, lg, o);
            vl += __shfl_down_sync(0xFFFFFFFFu, vl, o);
        }

        if (c == 0) {
            int s = __ldg(&seg[row]);
            if (s != curSeg) {               // sorted segments: rare
                if (curSeg >= 0) {
                    atomicAdd(&s_num[curSeg], accN);
                    atomicAdd(&s_den[curSeg], accD);
                }
                curSeg = s; accN = 0.0f; accD = 0.0f;
            }
            float e = __expf(lg);
            accD += e;
            accN = fmaf(e, vl, accN);
        }
    }
    if (c == 0 && curSeg >= 0) {
        atomicAdd(&s_num[curSeg], accN);
        atomicAdd(&s_den[curSeg], accD);
    }

    __syncthreads();
    if (t < NSEG && s_den[t] != 0.0f) {
        atomicAdd(&g_num[t], s_num[t]);
        atomicAdd(&g_den[t], s_den[t]);
    }

    // ---- last-block finalize + state reset ----
    __threadfence();
    __syncthreads();
    if (t == 0) {
        unsigned ticket = atomicAdd(&g_done, 1u);
        s_last = (ticket == (unsigned)(GRID - 1));
    }
    __syncthreads();
    if (!s_last) return;

    __shared__ float s_red[256];
    s_red[t] = bv[t] * Wo[t];
    __syncthreads();
#pragma unroll
    for (int o = 128; o > 0; o >>= 1) {
        if (t < o) s_red[t] += s_red[t + o];
        __syncthreads();
    }
    float c2 = s_red[0];
    float b  = bo[0];
    if (t < NSEG) {
        float den = g_den[t];
        out[t] = (den != 0.0f) ? (g_num[t] / den + c2 + b) : b;
    }
    __syncthreads();
    // reset globals so the next graph replay starts clean
    if (t < NSEG) { g_num[t] = 0.0f; g_den[t] = 0.0f; }
    if (t == 0)   { g_ready = 0u; g_done = 0u; __threadfence(); }
}

// ---------------- launch ----------------
extern "C" void kernel_launch(void* const* d_in, const int* in_sizes, int n_in,
                              void* d_out, int out_size) {
    const float* x   = (const float*)d_in[0];
    const int*   seg = (const int*)d_in[1];
    const float* Wk  = (const float*)d_in[2];
    // d_in[3] = bk (cancels in the segment softmax; unused)
    const float* Wv  = (const float*)d_in[4];
    const float* bv  = (const float*)d_in[5];
    const float* Wo  = (const float*)d_in[6];
    const float* bo  = (const float*)d_in[7];
    float* out = (float*)d_out;

    fused_kernel<<<GRID, 256>>>(x, seg, Wk, Wv, bv, Wo, bo, out);
}

// round 9
// speedup vs baseline: 1.0289x; 1.0073x over previous
#include <cuda_runtime.h>

#define NROWS 524288
#define DDIM  256
#define NSEG  128
#define ROWS_PER_BLOCK 64
#define P1_BLOCKS (NROWS / ROWS_PER_BLOCK)   // 8192

// ---------------- scratch (device globals; no allocation) ----------------
__device__ __align__(16) float g_u[DDIM];   // Wk @ ones
__device__ __align__(16) float g_v[DDIM];   // Wv @ Wo
__device__ float    g_num[NSEG];
__device__ float    g_den[NSEG];
__device__ unsigned g_done;                 // completion ticket

// ---------------- kernel 0: weight collapse + accumulator init ----------------
__global__ void __launch_bounds__(256) prep_kernel(const float* __restrict__ Wk,
                                                   const float* __restrict__ Wv,
                                                   const float* __restrict__ Wo) {
    __shared__ float swo[DDIM];
    int t = threadIdx.x;
    swo[t] = Wo[t];

    if (blockIdx.x == 0) {
        if (t < NSEG) { g_num[t] = 0.0f; g_den[t] = 0.0f; }
        if (t == 128) g_done = 0u;
    }
    __syncthreads();

    int lane = t & 31;
    int warp = t >> 5;
    int d = blockIdx.x * 8 + warp;

    const float4* wk = reinterpret_cast<const float4*>(Wk + (size_t)d * DDIM);
    const float4* wv = reinterpret_cast<const float4*>(Wv + (size_t)d * DDIM);
    const float4* wo = reinterpret_cast<const float4*>(swo);

    float su = 0.0f, sv = 0.0f;
#pragma unroll
    for (int i = 0; i < 2; i++) {
        int idx = lane + 32 * i;
        float4 k = wk[idx];
        float4 v = wv[idx];
        float4 o = wo[idx];
        su += (k.x + k.y) + (k.z + k.w);
        sv += v.x * o.x + v.y * o.y + v.z * o.z + v.w * o.w;
    }
#pragma unroll
    for (int o = 16; o > 0; o >>= 1) {
        su += __shfl_down_sync(0xFFFFFFFFu, su, o);
        sv += __shfl_down_sync(0xFFFFFFFFu, sv, o);
    }
    if (lane == 0) { g_u[d] = su; g_v[d] = sv; }
}

// ---------------- fused kernel (R6 structure, .cv loads) ----------------
// 16 lanes per row, 4 float4 chunks per thread, 2 rows per warp per pass,
// 64 rows per block (grid 8192). regs 32 -> 8 blocks/SM -> ~96% occ.
__global__ void __launch_bounds__(256, 7) fused_kernel(const float* __restrict__ x,
                                                       const int* __restrict__ seg,
                                                       const float* __restrict__ bv,
                                                       const float* __restrict__ Wo,
                                                       const float* __restrict__ bo,
                                                       float* __restrict__ out) {
    __shared__ __align__(16) float s_u[DDIM];
    __shared__ __align__(16) float s_v[DDIM];
    __shared__ float s_num[NSEG];
    __shared__ float s_den[NSEG];
    __shared__ bool  s_last;

    int t = threadIdx.x;
    s_u[t] = g_u[t];
    s_v[t] = g_v[t];
    if (t < NSEG) { s_num[t] = 0.0f; s_den[t] = 0.0f; }
    __syncthreads();

    int lane = t & 31;
    int c    = lane & 15;                    // lane within 16-lane row group
    int warp = t >> 5;
    int g    = (warp << 1) | (lane >> 4);    // group 0..15 within block

    const float4* su = reinterpret_cast<const float4*>(s_u);
    const float4* sv = reinterpret_cast<const float4*>(s_v);

    float accN = 0.0f, accD = 0.0f;
    int curSeg = -1;

#pragma unroll 1
    for (int r = 0; r < 4; r++) {
        int row = blockIdx.x * ROWS_PER_BLOCK + r * 16 + g;
        const float4* xp = reinterpret_cast<const float4*>(x + (size_t)row * DDIM);

        // segment id early so it overlaps the x loads
        int s = (c == 0) ? __ldg(&seg[row]) : 0;

        // 4 independent fetch-fresh loads (no L2 allocate for read-once data;
        // LDG.cv is the path the B300 LTS-cap measurement used)
        float4 x0 = __ldcv(&xp[c]);
        float4 x1 = __ldcv(&xp[c + 16]);
        float4 x2 = __ldcv(&xp[c + 32]);
        float4 x3 = __ldcv(&xp[c + 48]);

        float lg = 0.0f, vl = 0.0f;
        {
            float4 u0 = su[c],      v0 = sv[c];
            lg = fmaf(x0.x, u0.x, lg); lg = fmaf(x0.y, u0.y, lg);
            lg = fmaf(x0.z, u0.z, lg); lg = fmaf(x0.w, u0.w, lg);
            vl = fmaf(x0.x, v0.x, vl); vl = fmaf(x0.y, v0.y, vl);
            vl = fmaf(x0.z, v0.z, vl); vl = fmaf(x0.w, v0.w, vl);
        }
        {
            float4 u1 = su[c + 16], v1 = sv[c + 16];
            lg = fmaf(x1.x, u1.x, lg); lg = fmaf(x1.y, u1.y, lg);
            lg = fmaf(x1.z, u1.z, lg); lg = fmaf(x1.w, u1.w, lg);
            vl = fmaf(x1.x, v1.x, vl); vl = fmaf(x1.y, v1.y, vl);
            vl = fmaf(x1.z, v1.z, vl); vl = fmaf(x1.w, v1.w, vl);
        }
        {
            float4 u2 = su[c + 32], v2 = sv[c + 32];
            lg = fmaf(x2.x, u2.x, lg); lg = fmaf(x2.y, u2.y, lg);
            lg = fmaf(x2.z, u2.z, lg); lg = fmaf(x2.w, u2.w, lg);
            vl = fmaf(x2.x, v2.x, vl); vl = fmaf(x2.y, v2.y, vl);
            vl = fmaf(x2.z, v2.z, vl); vl = fmaf(x2.w, v2.w, vl);
        }
        {
            float4 u3 = su[c + 48], v3 = sv[c + 48];
            lg = fmaf(x3.x, u3.x, lg); lg = fmaf(x3.y, u3.y, lg);
            lg = fmaf(x3.z, u3.z, lg); lg = fmaf(x3.w, u3.w, lg);
            vl = fmaf(x3.x, v3.x, vl); vl = fmaf(x3.y, v3.y, vl);
            vl = fmaf(x3.z, v3.z, vl); vl = fmaf(x3.w, v3.w, vl);
        }

#pragma unroll
        for (int o = 8; o > 0; o >>= 1) {
            lg += __shfl_down_sync(0xFFFFFFFFu, lg, o);
            vl += __shfl_down_sync(0xFFFFFFFFu, vl, o);
        }

        if (c == 0) {
            if (s != curSeg) {               // sorted segments: rare
                if (curSeg >= 0) {
                    atomicAdd(&s_num[curSeg], accN);
                    atomicAdd(&s_den[curSeg], accD);
                }
                curSeg = s; accN = 0.0f; accD = 0.0f;
            }
            float e = __expf(lg);
            accD += e;
            accN = fmaf(e, vl, accN);
        }
    }
    if (c == 0 && curSeg >= 0) {
        atomicAdd(&s_num[curSeg], accN);
        atomicAdd(&s_den[curSeg], accD);
    }

    __syncthreads();
    if (t < NSEG && s_den[t] != 0.0f) {
        atomicAdd(&g_num[t], s_num[t]);
        atomicAdd(&g_den[t], s_den[t]);
    }

    // ---- last-block fused finalize ----
    __threadfence();
    __syncthreads();
    if (t == 0) {
        unsigned ticket = atomicAdd(&g_done, 1u);
        s_last = (ticket == (unsigned)(gridDim.x - 1));
    }
    __syncthreads();
    if (!s_last) return;

    __shared__ float s_red[256];
    s_red[t] = bv[t] * Wo[t];
    __syncthreads();
#pragma unroll
    for (int o = 128; o > 0; o >>= 1) {
        if (t < o) s_red[t] += s_red[t + o];
        __syncthreads();
    }
    float c2 = s_red[0];
    float b  = bo[0];
    if (t < NSEG) {
        float den = g_den[t];
        out[t] = (den != 0.0f) ? (g_num[t] / den + c2 + b) : b;
    }
}

// ---------------- launch ----------------
extern "C" void kernel_launch(void* const* d_in, const int* in_sizes, int n_in,
                              void* d_out, int out_size) {
    const float* x   = (const float*)d_in[0];
    const int*   seg = (const int*)d_in[1];
    const float* Wk  = (const float*)d_in[2];
    // d_in[3] = bk (cancels in the segment softmax; unused)
    const float* Wv  = (const float*)d_in[4];
    const float* bv  = (const float*)d_in[5];
    const float* Wo  = (const float*)d_in[6];
    const float* bo  = (const float*)d_in[7];
    float* out = (float*)d_out;

    prep_kernel<<<32, 256>>>(Wk, Wv, Wo);
    fused_kernel<<<P1_BLOCKS, 256>>>(x, seg, bv, Wo, bo, out);
}

// round 10
// speedup vs baseline: 1.1509x; 1.1186x over previous
#include <cuda_runtime.h>
#include <cuda_pipeline.h>

#define NROWS 524288
#define DDIM  256
#define NSEG  128
#define WARPS 8
#define ROWS_PER_WARP 8
#define ROWS_PER_BLOCK (WARPS * ROWS_PER_WARP)      // 64
#define GRID  (NROWS / ROWS_PER_BLOCK)              // 8192
#define RING  4                                     // rows buffered per warp

// ---------------- scratch (device globals; no allocation) ----------------
__device__ __align__(16) float g_u[DDIM];   // Wk @ ones
__device__ __align__(16) float g_v[DDIM];   // Wv @ Wo
__device__ float    g_num[NSEG];
__device__ float    g_den[NSEG];
__device__ unsigned g_done;                 // completion ticket

// ---------------- kernel 0: weight collapse + accumulator init ----------------
__global__ void __launch_bounds__(256) prep_kernel(const float* __restrict__ Wk,
                                                   const float* __restrict__ Wv,
                                                   const float* __restrict__ Wo) {
    __shared__ float swo[DDIM];
    int t = threadIdx.x;
    swo[t] = Wo[t];

    if (blockIdx.x == 0) {
        if (t < NSEG) { g_num[t] = 0.0f; g_den[t] = 0.0f; }
        if (t == 128) g_done = 0u;
    }
    __syncthreads();

    int lane = t & 31;
    int warp = t >> 5;
    int d = blockIdx.x * 8 + warp;

    const float4* wk = reinterpret_cast<const float4*>(Wk + (size_t)d * DDIM);
    const float4* wv = reinterpret_cast<const float4*>(Wv + (size_t)d * DDIM);
    const float4* wo = reinterpret_cast<const float4*>(swo);

    float su = 0.0f, sv = 0.0f;
#pragma unroll
    for (int i = 0; i < 2; i++) {
        int idx = lane + 32 * i;
        float4 k = wk[idx];
        float4 v = wv[idx];
        float4 o = wo[idx];
        su += (k.x + k.y) + (k.z + k.w);
        sv += v.x * o.x + v.y * o.y + v.z * o.z + v.w * o.w;
    }
#pragma unroll
    for (int o = 16; o > 0; o >>= 1) {
        su += __shfl_down_sync(0xFFFFFFFFu, su, o);
        sv += __shfl_down_sync(0xFFFFFFFFu, sv, o);
    }
    if (lane == 0) { g_u[d] = su; g_v[d] = sv; }
}

// ---------------- fused kernel: per-warp cp.async ring pipeline ----------------
// Each warp owns 8 consecutive rows and a private 4-row (4KB) smem ring.
// cp.async keeps 3 rows (3KB) in flight per warp continuously ->
// ~144KB in flight per SM (vs ~40KB on the LDG path). No block-wide syncs in
// the hot loop; each thread reads back only the chunks it copied, so
// __pipeline_wait_prior alone gives visibility.
__global__ void __launch_bounds__(256, 6)
fused_kernel(const float* __restrict__ x, const int* __restrict__ seg,
             const float* __restrict__ bv, const float* __restrict__ Wo,
             const float* __restrict__ bo, float* __restrict__ out)
{
    __shared__ __align__(16) float4 ring[WARPS][RING][DDIM / 4];  // 32 KB
    __shared__ float s_num[NSEG];
    __shared__ float s_den[NSEG];
    __shared__ bool  s_last;

    int t    = threadIdx.x;
    int lane = t & 31;
    int warp = t >> 5;

    if (t < NSEG) { s_num[t] = 0.0f; s_den[t] = 0.0f; }
    __syncthreads();

    // weights in registers: chunks lane and lane+32 (matches copied chunks)
    const float4* gu4 = reinterpret_cast<const float4*>(g_u);
    const float4* gv4 = reinterpret_cast<const float4*>(g_v);
    float4 ua = gu4[lane], ub = gu4[32 + lane];
    float4 va = gv4[lane], vb = gv4[32 + lane];

    int row0 = blockIdx.x * ROWS_PER_BLOCK + warp * ROWS_PER_WARP;
    const float4* x4 = reinterpret_cast<const float4*>(x);

    // prologue: rows 0..2 in flight (one commit group per row per thread)
#pragma unroll
    for (int r = 0; r < 3; r++) {
        const float4* src = x4 + (size_t)(row0 + r) * (DDIM / 4);
        float4* dst = &ring[warp][r & (RING - 1)][0];
        __pipeline_memcpy_async(dst + lane,      src + lane,      16);
        __pipeline_memcpy_async(dst + lane + 32, src + lane + 32, 16);
        __pipeline_commit();
    }

    float accN = 0.0f, accD = 0.0f;
    int curSeg = -1;

#pragma unroll
    for (int r = 0; r < ROWS_PER_WARP; r++) {
        if (r + 3 < ROWS_PER_WARP) {
            const float4* src = x4 + (size_t)(row0 + r + 3) * (DDIM / 4);
            float4* dst = &ring[warp][(r + 3) & (RING - 1)][0];
            __pipeline_memcpy_async(dst + lane,      src + lane,      16);
            __pipeline_memcpy_async(dst + lane + 32, src + lane + 32, 16);
            __pipeline_commit();
            __pipeline_wait_prior(3);         // row r landed; 3 rows in flight
        } else {
            __pipeline_wait_prior(ROWS_PER_WARP - 1 - r);  // drain tail
        }

        const float4* slot = &ring[warp][r & (RING - 1)][0];
        float4 x0 = slot[lane];
        float4 x1 = slot[lane + 32];

        float lg, vl;
        lg = x0.x * ua.x;           vl = x0.x * va.x;
        lg = fmaf(x0.y, ua.y, lg);  vl = fmaf(x0.y, va.y, vl);
        lg = fmaf(x0.z, ua.z, lg);  vl = fmaf(x0.z, va.z, vl);
        lg = fmaf(x0.w, ua.w, lg);  vl = fmaf(x0.w, va.w, vl);
        lg = fmaf(x1.x, ub.x, lg);  vl = fmaf(x1.x, vb.x, vl);
        lg = fmaf(x1.y, ub.y, lg);  vl = fmaf(x1.y, vb.y, vl);
        lg = fmaf(x1.z, ub.z, lg);  vl = fmaf(x1.z, vb.z, vl);
        lg = fmaf(x1.w, ub.w, lg);  vl = fmaf(x1.w, vb.w, vl);

#pragma unroll
        for (int o = 16; o > 0; o >>= 1) {
            lg += __shfl_down_sync(0xFFFFFFFFu, lg, o);
            vl += __shfl_down_sync(0xFFFFFFFFu, vl, o);
        }

        if (lane == 0) {
            int s = __ldg(&seg[row0 + r]);
            if (s != curSeg) {               // sorted segments: rare
                if (curSeg >= 0) {
                    atomicAdd(&s_num[curSeg], accN);
                    atomicAdd(&s_den[curSeg], accD);
                }
                curSeg = s; accN = 0.0f; accD = 0.0f;
            }
            float e = __expf(lg);
            accD += e;
            accN = fmaf(e, vl, accN);
        }
    }
    if (lane == 0 && curSeg >= 0) {
        atomicAdd(&s_num[curSeg], accN);
        atomicAdd(&s_den[curSeg], accD);
    }

    __syncthreads();
    if (t < NSEG && s_den[t] != 0.0f) {
        atomicAdd(&g_num[t], s_num[t]);
        atomicAdd(&g_den[t], s_den[t]);
    }

    // ---- last-block fused finalize ----
    __threadfence();
    __syncthreads();
    if (t == 0) {
        unsigned ticket = atomicAdd(&g_done, 1u);
        s_last = (ticket == (unsigned)(gridDim.x - 1));
    }
    __syncthreads();
    if (!s_last) return;

    __shared__ float s_red[256];
    s_red[t] = bv[t] * Wo[t];
    __syncthreads();
#pragma unroll
    for (int o = 128; o > 0; o >>= 1) {
        if (t < o) s_red[t] += s_red[t + o];
        __syncthreads();
    }
    float c2 = s_red[0];
    float b  = bo[0];
    if (t < NSEG) {
        float den = g_den[t];
        out[t] = (den != 0.0f) ? (g_num[t] / den + c2 + b) : b;
    }
}

// ---------------- launch ----------------
extern "C" void kernel_launch(void* const* d_in, const int* in_sizes, int n_in,
                              void* d_out, int out_size) {
    const float* x   = (const float*)d_in[0];
    const int*   seg = (const int*)d_in[1];
    const float* Wk  = (const float*)d_in[2];
    // d_in[3] = bk (cancels in the segment softmax; unused)
    const float* Wv  = (const float*)d_in[4];
    const float* bv  = (const float*)d_in[5];
    const float* Wo  = (const float*)d_in[6];
    const float* bo  = (const float*)d_in[7];
    float* out = (float*)d_out;

    prep_kernel<<<32, 256>>>(Wk, Wv, Wo);
    fused_kernel<<<GRID, 256>>>(x, seg, bv, Wo, bo, out);
}